// round 2
// baseline (speedup 1.0000x reference)
#include <cuda_runtime.h>
#include <math.h>
#include <stdint.h>

// ---------------- problem constants ----------------
#define BATCH 2
#define SEQ   4096
#define DM    768
#define DI    1536
#define NH    24
#define HD    64
#define DS    128
#define CHK   32
#define NC    128              // SEQ/CHK
#define CONV_DIM 1792          // DI + 2*DS
#define DPROJ 3352             // 2*DI + 2*DS + NH
#define DT_OFF 3328            // DI + CONV_DIM
#define ROWS  (BATCH*SEQ)      // 8192
#define EPS   1e-6f

// ---------------- scratch (device globals; no allocation allowed) ----------
__device__ float g_y[(size_t)ROWS*DM];          // pre-norm output
__device__ float g_zx[(size_t)ROWS*DPROJ];      // in_proj output
__device__ float g_xbc[(size_t)ROWS*CONV_DIM];  // post conv+silu (+rope on B,C)
__device__ float g_dt[(size_t)ROWS*NH];         // softplus(dt+bias)
__device__ float g_states[(size_t)BATCH*NC*NH*HD*DS]; // chunk states -> prev (in place)
__device__ float g_cd[BATCH*NC*NH];             // chunk decay
__device__ float g_yv[(size_t)ROWS*DI];         // Yd, then final gated yv
__device__ float g_out[(size_t)ROWS*DM];        // out_proj result

// ---------------- helpers ----------------
__device__ __forceinline__ float block_reduce_sum(float v) {
    __shared__ float sh[8];
    int lane = threadIdx.x & 31, w = threadIdx.x >> 5;
#pragma unroll
    for (int o = 16; o; o >>= 1) v += __shfl_down_sync(0xffffffffu, v, o);
    if (lane == 0) sh[w] = v;
    __syncthreads();
    if (w == 0) {
        v = (lane < 8) ? sh[lane] : 0.f;
#pragma unroll
        for (int o = 4; o; o >>= 1) v += __shfl_down_sync(0xffffffffu, v, o);
        if (lane == 0) sh[0] = v;
    }
    __syncthreads();
    return sh[0];
}

__device__ __forceinline__ float siluf(float x) { return x / (1.f + expf(-x)); }

// ---------------- 1) pre-RMSNorm ----------------
__global__ void __launch_bounds__(256) k_rms_pre(const float* __restrict__ x,
                                                 const float* __restrict__ sc) {
    int row = blockIdx.x, t = threadIdx.x;
    const float* xr = x + (size_t)row * DM;
    float v0 = xr[t], v1 = xr[t + 256], v2 = xr[t + 512];
    float ss = block_reduce_sum(v0 * v0 + v1 * v1 + v2 * v2);
    float inv = rsqrtf(ss * (1.0f / DM) + EPS);
    float* yr = g_y + (size_t)row * DM;
    yr[t]       = v0 * inv * (1.f + sc[t]);
    yr[t + 256] = v1 * inv * (1.f + sc[t + 256]);
    yr[t + 512] = v2 * inv * (1.f + sc[t + 512]);
}

// ---------------- generic fp32 SGEMM (128x128x8, 8x8/thread, double-buffered) ----
__device__ __forceinline__ void sgemm_dev(const float* __restrict__ A,
                                          const float* __restrict__ B,
                                          float* __restrict__ C,
                                          int M, int N, int K) {
    __shared__ float As[2][8][128];
    __shared__ float Bs[2][8][128];
    const int tid = threadIdx.x;
    const int bx = blockIdx.x, by = blockIdx.y;
    const int tx = tid & 15, ty = tid >> 4;
    const int aRow = tid >> 1;
    const int aCol = (tid & 1) << 2;
    const int bRow = tid >> 5;
    const int bCol = (tid & 31) << 2;
    const int bColG = bx * 128 + bCol;
    const float* Ap = A + (size_t)(by * 128 + aRow) * K + aCol;

    float acc[8][8];
#pragma unroll
    for (int i = 0; i < 8; i++)
#pragma unroll
        for (int j = 0; j < 8; j++) acc[i][j] = 0.f;

    float4 ar;
    float br[4];
    // tile 0
    ar = *(const float4*)Ap;
    {
        const float* Bp = B + (size_t)bRow * N;
        if (bColG + 3 < N) {
            float4 v = *(const float4*)(Bp + bColG);
            br[0] = v.x; br[1] = v.y; br[2] = v.z; br[3] = v.w;
        } else {
#pragma unroll
            for (int e = 0; e < 4; e++) br[e] = (bColG + e < N) ? Bp[bColG + e] : 0.f;
        }
    }
    As[0][aCol + 0][aRow] = ar.x;
    As[0][aCol + 1][aRow] = ar.y;
    As[0][aCol + 2][aRow] = ar.z;
    As[0][aCol + 3][aRow] = ar.w;
    *(float4*)&Bs[0][bRow][bCol] = make_float4(br[0], br[1], br[2], br[3]);
    __syncthreads();

    const int nt = K >> 3;
    int buf = 0;
    for (int tI = 0; tI < nt; tI++) {
        if (tI + 1 < nt) {
            int k0 = (tI + 1) << 3;
            ar = *(const float4*)(Ap + k0);
            const float* Bp = B + (size_t)(k0 + bRow) * N;
            if (bColG + 3 < N) {
                float4 v = *(const float4*)(Bp + bColG);
                br[0] = v.x; br[1] = v.y; br[2] = v.z; br[3] = v.w;
            } else {
#pragma unroll
                for (int e = 0; e < 4; e++) br[e] = (bColG + e < N) ? Bp[bColG + e] : 0.f;
            }
        }
#pragma unroll
        for (int kk = 0; kk < 8; kk++) {
            float a[8], bb[8];
#pragma unroll
            for (int i = 0; i < 8; i++) a[i] = As[buf][kk][ty * 8 + i];
#pragma unroll
            for (int j = 0; j < 8; j++) bb[j] = Bs[buf][kk][tx * 8 + j];
#pragma unroll
            for (int i = 0; i < 8; i++)
#pragma unroll
                for (int j = 0; j < 8; j++) acc[i][j] += a[i] * bb[j];
        }
        if (tI + 1 < nt) {
            int nb = buf ^ 1;
            As[nb][aCol + 0][aRow] = ar.x;
            As[nb][aCol + 1][aRow] = ar.y;
            As[nb][aCol + 2][aRow] = ar.z;
            As[nb][aCol + 3][aRow] = ar.w;
            *(float4*)&Bs[nb][bRow][bCol] = make_float4(br[0], br[1], br[2], br[3]);
            buf = nb;
        }
        __syncthreads();
    }
#pragma unroll
    for (int i = 0; i < 8; i++) {
        size_t r = (size_t)(by * 128 + ty * 8 + i) * N;
#pragma unroll
        for (int j = 0; j < 8; j++) {
            int cix = bx * 128 + tx * 8 + j;
            if (cix < N) C[r + cix] = acc[i][j];
        }
    }
}

__global__ void __launch_bounds__(256) k_gemm_in(const float* __restrict__ W) {
    sgemm_dev(g_y, W, g_zx, ROWS, DPROJ, DM);
}
__global__ void __launch_bounds__(256) k_gemm_out(const float* __restrict__ W) {
    sgemm_dev(g_yv, W, g_out, ROWS, DM, DI);
}

// ---------------- 3) depthwise conv + SiLU + RoPE + dt softplus ----------------
__global__ void __launch_bounds__(256) k_conv(const float* __restrict__ conv_w,
                                              const float* __restrict__ conv_b,
                                              const float* __restrict__ dt_bias) {
    const int row = blockIdx.x;          // b*SEQ + l
    const int l = row & (SEQ - 1);
    const int b = row >> 12;
    const int t = threadIdx.x;
    __shared__ float s[CONV_DIM];

    for (int ch = t; ch < CONV_DIM; ch += 256) {
        float acc = conv_b[ch];
#pragma unroll
        for (int i = 0; i < 4; i++) {
            int ls = l + i - 3;
            if (ls >= 0)
                acc += g_zx[(size_t)(b * SEQ + ls) * DPROJ + DI + ch] * conv_w[ch * 4 + i];
        }
        s[ch] = siluf(acc);
    }
    __syncthreads();

    // RoPE on first 64 dims of B (1536..) and C (1664..)
    float r1 = 0.f, r2 = 0.f;
    int jb = 0;
    if (t < 64) {
        int which = t >> 5;
        int j = t & 31;
        jb = DI + which * DS + j;
        float freq = powf(10000.f, -(float)j / 32.f);
        float ang = (float)l * freq;
        float sn, cs;
        sincosf(ang, &sn, &cs);
        float v1 = s[jb], v2 = s[jb + 32];
        r1 = v1 * cs - v2 * sn;
        r2 = v1 * sn + v2 * cs;
    }
    __syncthreads();
    if (t < 64) { s[jb] = r1; s[jb + 32] = r2; }
    __syncthreads();

    float* dst = g_xbc + (size_t)row * CONV_DIM;
    for (int ch = t; ch < CONV_DIM; ch += 256) dst[ch] = s[ch];

    if (t < NH) {
        float v = g_zx[(size_t)row * DPROJ + DT_OFF + t] + dt_bias[t];
        g_dt[(size_t)row * NH + t] = (v > 20.f) ? v : log1pf(expf(v));
    }
}

// ---------------- 4) intra-chunk: Yd + per-chunk states + chunk decay ----------
__global__ void __launch_bounds__(256) k_chunk(const float* __restrict__ A_log) {
    const int h = blockIdx.x, c = blockIdx.y, b = blockIdx.z;
    __shared__ float Bs[32][129];
    __shared__ float Cs[32][129];
    __shared__ float Xs[32][65];
    __shared__ float att[32][33];
    __shared__ float dts[32], dacs[32], coeff[32];
    const int t = threadIdx.x;
    const int row0 = b * SEQ + c * CHK;

    for (int idx = t; idx < 32 * 128; idx += 256) {
        int i = idx >> 7, n = idx & 127;
        size_t g = (size_t)(row0 + i) * CONV_DIM;
        Bs[i][n] = g_xbc[g + DI + n];
        Cs[i][n] = g_xbc[g + DI + DS + n];
    }
    for (int idx = t; idx < 32 * 64; idx += 256) {
        int i = idx >> 6, p = idx & 63;
        Xs[i][p] = g_xbc[(size_t)(row0 + i) * CONV_DIM + h * HD + p];
    }
    if (t < 32) dts[t] = g_dt[(size_t)(row0 + t) * NH + h];
    __syncthreads();
    if (t == 0) {
        float A = -expf(A_log[h]);
        float cs = 0.f;
        for (int i = 0; i < 32; i++) { cs += dts[i] * A; dacs[i] = cs; }
    }
    __syncthreads();
    if (t < 32) coeff[t] = dts[t] * expf(dacs[31] - dacs[t]);

    // att[i][j] = (C_i . B_j) * exp(dacs_i - dacs_j) * dt_j   (lower-tri)
    {
        int i = t >> 3, j0 = (t & 7) << 2;
        float s0 = 0, s1 = 0, s2 = 0, s3 = 0;
        for (int n = 0; n < 128; n++) {
            float cv = Cs[i][n];
            s0 += cv * Bs[j0 + 0][n];
            s1 += cv * Bs[j0 + 1][n];
            s2 += cv * Bs[j0 + 2][n];
            s3 += cv * Bs[j0 + 3][n];
        }
        float di = dacs[i];
        att[i][j0 + 0] = (j0 + 0 <= i) ? s0 * expf(di - dacs[j0 + 0]) * dts[j0 + 0] : 0.f;
        att[i][j0 + 1] = (j0 + 1 <= i) ? s1 * expf(di - dacs[j0 + 1]) * dts[j0 + 1] : 0.f;
        att[i][j0 + 2] = (j0 + 2 <= i) ? s2 * expf(di - dacs[j0 + 2]) * dts[j0 + 2] : 0.f;
        att[i][j0 + 3] = (j0 + 3 <= i) ? s3 * expf(di - dacs[j0 + 3]) * dts[j0 + 3] : 0.f;
    }
    __syncthreads();

    // Yd[i][p] = sum_{j<=i} att[i][j] * X[j][p]
    {
        int i = t >> 3, p0 = (t & 7) << 3;
        float acc[8] = {0, 0, 0, 0, 0, 0, 0, 0};
        for (int j = 0; j <= i; j++) {
            float a = att[i][j];
#pragma unroll
            for (int q = 0; q < 8; q++) acc[q] += a * Xs[j][p0 + q];
        }
        size_t g = (size_t)(row0 + i) * DI + h * HD + p0;
#pragma unroll
        for (int q = 0; q < 8; q++) g_yv[g + q] = acc[q];
    }

    // states[p][n] = sum_l coeff_l * B[l][n] * X[l][p]
    {
        int n = t & 127;
        int pb = t >> 7; // 0 or 1
        float Bv[32];
#pragma unroll
        for (int l = 0; l < 32; l++) Bv[l] = coeff[l] * Bs[l][n];
        size_t sb = ((size_t)((b * NC + c) * NH + h)) * (HD * DS);
        for (int e = 0; e < 32; e++) {
            int p = pb + 2 * e;
            float s = 0.f;
#pragma unroll
            for (int l = 0; l < 32; l++) s += Bv[l] * Xs[l][p];
            g_states[sb + (size_t)p * DS + n] = s;
        }
    }
    if (t == 0) g_cd[(b * NC + c) * NH + h] = expf(dacs[31]);
}

// ---------------- 5) sequential inter-chunk scan (prev written in-place) --------
__global__ void __launch_bounds__(256) k_scan() {
    const int bh = blockIdx.x;
    const int b = bh / NH, h = bh % NH;
    const int t = threadIdx.x;
    float s[32];
#pragma unroll
    for (int e = 0; e < 32; e++) s[e] = 0.f;
    for (int c = 0; c < NC; c++) {
        size_t base = ((size_t)((b * NC + c) * NH + h)) * (HD * DS);
        float cdv = g_cd[(b * NC + c) * NH + h];
#pragma unroll
        for (int e = 0; e < 32; e++) {
            size_t off = base + (size_t)e * 256 + t;
            float tmp = g_states[off];
            g_states[off] = s[e];        // prev (state before this chunk)
            s[e] = s[e] * cdv + tmp;     // carry update
        }
    }
}

// ---------------- 6) Yo + D*xin + silu(z) gating -> final yv --------------------
__global__ void __launch_bounds__(256) k_yo(const float* __restrict__ A_log,
                                            const float* __restrict__ Dp) {
    const int h = blockIdx.x, c = blockIdx.y, b = blockIdx.z;
    __shared__ float Cs[32][129];
    __shared__ float Ps[64][65];
    __shared__ float dts[32], dacs[32];
    const int t = threadIdx.x;
    const int row0 = b * SEQ + c * CHK;

    for (int idx = t; idx < 32 * 128; idx += 256) {
        int i = idx >> 7, n = idx & 127;
        Cs[i][n] = g_xbc[(size_t)(row0 + i) * CONV_DIM + DI + DS + n];
    }
    if (t < 32) dts[t] = g_dt[(size_t)(row0 + t) * NH + h];
    __syncthreads();
    if (t == 0) {
        float A = -expf(A_log[h]);
        float cs = 0.f;
        for (int i = 0; i < 32; i++) { cs += dts[i] * A; dacs[i] = cs; }
    }

    const int i = t >> 3, p0 = (t & 7) << 3;
    float acc[8] = {0, 0, 0, 0, 0, 0, 0, 0};
    size_t pb = ((size_t)((b * NC + c) * NH + h)) * (HD * DS);
    for (int half = 0; half < 2; half++) {
        __syncthreads();
        for (int idx = t; idx < 64 * 64; idx += 256) {
            int p = idx >> 6, n = idx & 63;
            Ps[p][n] = g_states[pb + (size_t)p * DS + half * 64 + n];
        }
        __syncthreads();
        for (int n = 0; n < 64; n++) {
            float cv = Cs[i][half * 64 + n];
#pragma unroll
            for (int q = 0; q < 8; q++) acc[q] += cv * Ps[p0 + q][n];
        }
    }
    float ei = expf(dacs[i]);
    float dph = Dp[h];
    size_t row = row0 + i;
#pragma unroll
    for (int q = 0; q < 8; q++) {
        int p = p0 + q;
        float xin = g_xbc[row * CONV_DIM + h * HD + p];
        float z = g_zx[row * DPROJ + h * HD + p];
        size_t yi = row * DI + h * HD + p;
        float Y = g_yv[yi] + ei * acc[q] + dph * xin;
        g_yv[yi] = Y * siluf(z);
    }
}

// ---------------- 8) post-RMSNorm + residual -> d_out ---------------------------
__global__ void __launch_bounds__(256) k_final(const float* __restrict__ x,
                                               const float* __restrict__ sc,
                                               float* __restrict__ out) {
    int row = blockIdx.x, t = threadIdx.x;
    const float* gr = g_out + (size_t)row * DM;
    float v0 = gr[t], v1 = gr[t + 256], v2 = gr[t + 512];
    float ss = block_reduce_sum(v0 * v0 + v1 * v1 + v2 * v2);
    float inv = rsqrtf(ss * (1.0f / DM) + EPS);
    const float* xr = x + (size_t)row * DM;
    size_t o = (size_t)row * DM;
    out[o + t]       = xr[t]       + v0 * inv * (1.f + sc[t]);
    out[o + t + 256] = xr[t + 256] + v1 * inv * (1.f + sc[t + 256]);
    out[o + t + 512] = xr[t + 512] + v2 * inv * (1.f + sc[t + 512]);
}

// ---------------- launch -----------------------------------------------------
extern "C" void kernel_launch(void* const* d_in, const int* in_sizes, int n_in,
                              void* d_out, int out_size) {
    const float* x          = (const float*)d_in[0];
    const float* pre_scale  = (const float*)d_in[1];
    const float* post_scale = (const float*)d_in[2];
    const float* W_in       = (const float*)d_in[3];
    const float* conv_w     = (const float*)d_in[4];
    const float* conv_b     = (const float*)d_in[5];
    const float* dt_bias    = (const float*)d_in[6];
    const float* A_log      = (const float*)d_in[7];
    const float* D_param    = (const float*)d_in[8];
    const float* W_out      = (const float*)d_in[9];
    float* out = (float*)d_out;

    k_rms_pre<<<ROWS, 256>>>(x, pre_scale);
    k_gemm_in<<<dim3((DPROJ + 127) / 128, ROWS / 128), 256>>>(W_in);
    k_conv<<<ROWS, 256>>>(conv_w, conv_b, dt_bias);
    k_chunk<<<dim3(NH, NC, BATCH), 256>>>(A_log);
    k_scan<<<BATCH * NH, 256>>>();
    k_yo<<<dim3(NH, NC, BATCH), 256>>>(A_log, D_param);
    k_gemm_out<<<dim3(DM / 128, ROWS / 128), 256>>>(W_out);
    k_final<<<ROWS, 256>>>(x, post_scale, out);
}

// round 4
// speedup vs baseline: 1.4599x; 1.4599x over previous
#include <cuda_runtime.h>
#include <cuda_bf16.h>
#include <math.h>
#include <stdint.h>

// ---------------- problem constants ----------------
#define BATCH 2
#define SEQ   4096
#define DM    768
#define DI    1536
#define NH    24
#define HD    64
#define DS    128
#define CHK   32
#define NC    128
#define CONV_DIM 1792
#define DPROJ 3352
#define DT_OFF 3328
#define ROWS  (BATCH*SEQ)
#define EPS   1e-6f

#define N1PAD 3456            // in_proj N padded to 27*128

// GEMM smem: 4 tiles (Ah,Al,Bh,Bl) x 128 rows x 80B, double buffered
#define TILE_B  10240
#define STAGE_B (4*TILE_B)          // 40960
#define SMEM_GEMM_BYTES (2*STAGE_B) // 81920

// ---------------- scratch ----------------
__device__ __nv_bfloat16 g_y_h[(size_t)ROWS*DM];
__device__ __nv_bfloat16 g_y_l[(size_t)ROWS*DM];
__device__ __nv_bfloat16 g_winT_h[(size_t)N1PAD*DM];
__device__ __nv_bfloat16 g_winT_l[(size_t)N1PAD*DM];
__device__ __nv_bfloat16 g_woutT_h[(size_t)DM*DI];
__device__ __nv_bfloat16 g_woutT_l[(size_t)DM*DI];
__device__ __nv_bfloat16 g_yv_h[(size_t)ROWS*DI];
__device__ __nv_bfloat16 g_yv_l[(size_t)ROWS*DI];
__device__ float g_zx[(size_t)ROWS*DPROJ];
__device__ float g_xbc[(size_t)ROWS*CONV_DIM];
__device__ float g_dt[(size_t)ROWS*NH];
__device__ float g_states[(size_t)BATCH*NC*NH*HD*DS];
__device__ float g_cd[BATCH*NC*NH];
__device__ float g_yv[(size_t)ROWS*DI];        // Yd intermediate
__device__ float g_out[(size_t)ROWS*DM];

// ---------------- PTX helpers ----------------
__device__ __forceinline__ uint32_t smem_u32(const void* p) {
    uint32_t a;
    asm("{ .reg .u64 t; cvta.to.shared.u64 t, %1; cvt.u32.u64 %0, t; }" : "=r"(a) : "l"(p));
    return a;
}
#define CP16(dst, src)      asm volatile("cp.async.cg.shared.global [%0], [%1], 16;" :: "r"(dst), "l"(src))
#define CP_COMMIT()         asm volatile("cp.async.commit_group;" ::: "memory")
#define CP_WAIT1()          asm volatile("cp.async.wait_group 1;" ::: "memory")
#define CP_WAIT0()          asm volatile("cp.async.wait_group 0;" ::: "memory")

#define LDM4(r0, r1, r2, r3, addr) \
    asm volatile("ldmatrix.sync.aligned.m8n8.x4.shared.b16 {%0,%1,%2,%3}, [%4];" \
        : "=r"(r0), "=r"(r1), "=r"(r2), "=r"(r3) : "r"(addr))

#define MMA16816(c, a, b) \
    asm volatile("mma.sync.aligned.m16n8k16.row.col.f32.bf16.bf16.f32 " \
        "{%0,%1,%2,%3}, {%4,%5,%6,%7}, {%8,%9}, {%0,%1,%2,%3};" \
        : "+f"((c)[0]), "+f"((c)[1]), "+f"((c)[2]), "+f"((c)[3]) \
        : "r"((a)[0]), "r"((a)[1]), "r"((a)[2]), "r"((a)[3]), \
          "r"((b)[0]), "r"((b)[1]))

__device__ __forceinline__ void split2(float v, __nv_bfloat16& h, __nv_bfloat16& l) {
    h = __float2bfloat16_rn(v);
    l = __float2bfloat16_rn(v - __bfloat162float(h));
}
__device__ __forceinline__ float siluf(float x) { return x / (1.f + expf(-x)); }

__device__ __forceinline__ float block_reduce_sum(float v) {
    __shared__ float sh[8];
    int lane = threadIdx.x & 31, w = threadIdx.x >> 5;
#pragma unroll
    for (int o = 16; o; o >>= 1) v += __shfl_down_sync(0xffffffffu, v, o);
    if (lane == 0) sh[w] = v;
    __syncthreads();
    if (w == 0) {
        v = (lane < 8) ? sh[lane] : 0.f;
#pragma unroll
        for (int o = 4; o; o >>= 1) v += __shfl_down_sync(0xffffffffu, v, o);
        if (lane == 0) sh[0] = v;
    }
    __syncthreads();
    return sh[0];
}

// ---------------- 1) pre-RMSNorm -> bf16 hi/lo ----------------
__global__ void __launch_bounds__(256) k_rms_pre(const float* __restrict__ x,
                                                 const float* __restrict__ sc) {
    int row = blockIdx.x, t = threadIdx.x;
    const float* xr = x + (size_t)row * DM;
    float v0 = xr[t], v1 = xr[t + 256], v2 = xr[t + 512];
    float ss = block_reduce_sum(v0 * v0 + v1 * v1 + v2 * v2);
    float inv = rsqrtf(ss * (1.0f / DM) + EPS);
    __nv_bfloat16* yh = g_y_h + (size_t)row * DM;
    __nv_bfloat16* yl = g_y_l + (size_t)row * DM;
    float y0 = v0 * inv * (1.f + sc[t]);
    float y1 = v1 * inv * (1.f + sc[t + 256]);
    float y2 = v2 * inv * (1.f + sc[t + 512]);
    split2(y0, yh[t], yl[t]);
    split2(y1, yh[t + 256], yl[t + 256]);
    split2(y2, yh[t + 512], yl[t + 512]);
}

// ---------------- weight transpose + split ----------------
__global__ void __launch_bounds__(256) k_wsplit(const float* __restrict__ W,
                                                __nv_bfloat16* __restrict__ Th,
                                                __nv_bfloat16* __restrict__ Tl,
                                                int Kin, int Nin, int Npad) {
    __shared__ float tile[32][33];
    int tx = threadIdx.x & 31, ty = threadIdx.x >> 5;
    int n0 = blockIdx.x * 32, k0 = blockIdx.y * 32;
#pragma unroll
    for (int i = 0; i < 4; i++) {
        int k = k0 + ty + i * 8, n = n0 + tx;
        tile[ty + i * 8][tx] = (k < Kin && n < Nin) ? W[(size_t)k * Nin + n] : 0.f;
    }
    __syncthreads();
#pragma unroll
    for (int i = 0; i < 4; i++) {
        int n = n0 + ty + i * 8, k = k0 + tx;
        if (n < Npad && k < Kin) {
            float v = tile[tx][ty + i * 8];
            __nv_bfloat16 h, l;
            split2(v, h, l);
            Th[(size_t)n * Kin + k] = h;
            Tl[(size_t)n * Kin + k] = l;
        }
    }
}

// ---------------- bf16-split GEMM via mma.sync: C[M,Nc] = A[M,K] * B^T -------
// A hi/lo: [M][K] bf16.  B hi/lo: [Npad][K] bf16 (pre-transposed weights).
// Block 128x128, 8 warps (2x4), warp tile 64x32 (4x4 m16n8k16 frags), K-stage 32.
template <int K>
__global__ void __launch_bounds__(256) k_gemm_mma(const __nv_bfloat16* __restrict__ Ah,
                                                  const __nv_bfloat16* __restrict__ Al,
                                                  const __nv_bfloat16* __restrict__ Bh,
                                                  const __nv_bfloat16* __restrict__ Bl,
                                                  float* __restrict__ C, int Nc) {
    constexpr int NS = K / 32;
    extern __shared__ char smem[];
    const uint32_t sb = smem_u32(smem);
    const int tid = threadIdx.x;
    const int wid = tid >> 5, lane = tid & 31;
    const int warp_m = wid & 1, warp_n = wid >> 1;
    const int row0 = blockIdx.y * 128;
    const int n0   = blockIdx.x * 128;

    const __nv_bfloat16* srcs[4] = { Ah + (size_t)row0 * K, Al + (size_t)row0 * K,
                                     Bh + (size_t)n0  * K, Bl + (size_t)n0  * K };

    auto load_stage = [&](int s) {
        uint32_t base = sb + (uint32_t)(s & 1) * STAGE_B;
        int k0 = s * 32;
#pragma unroll
        for (int t4 = 0; t4 < 4; t4++) {
            const __nv_bfloat16* src = srcs[t4];
            uint32_t tb = base + (uint32_t)t4 * TILE_B;
#pragma unroll
            for (int it = 0; it < 2; it++) {
                int idx = it * 256 + tid;           // 0..511
                int r = idx >> 2, cs = idx & 3;
                CP16(tb + (uint32_t)(r * 80 + cs * 16), src + (size_t)r * K + k0 + cs * 8);
            }
        }
        CP_COMMIT();
    };

    load_stage(0);
    load_stage(1);

    float acc[4][4][4];
#pragma unroll
    for (int i = 0; i < 4; i++)
#pragma unroll
        for (int j = 0; j < 4; j++)
#pragma unroll
            for (int q = 0; q < 4; q++) acc[i][j][q] = 0.f;

    // per-lane ldmatrix offsets (elements)
    const int a_r = (lane & 7) + ((lane >> 3) & 1) * 8;   // row within 16
    const int a_c = ((lane >> 4) & 1) * 8;                // k within 16
    const int b_n = (lane & 7) + ((lane >> 4) & 1) * 8;   // n within 16 (pair of 8-tiles)
    const int b_k = ((lane >> 3) & 1) * 8;                // k within 16

    for (int s = 0; s < NS; s++) {
        if (s < NS - 1) { CP_WAIT1(); } else { CP_WAIT0(); }
        __syncthreads();
        uint32_t base = sb + (uint32_t)(s & 1) * STAGE_B;
#pragma unroll
        for (int kc = 0; kc < 2; kc++) {
            uint32_t bh[4][2], bl[4][2];
#pragma unroll
            for (int pair = 0; pair < 2; pair++) {
                uint32_t boff = (uint32_t)(((warp_n * 32 + pair * 16 + b_n) * 40 + kc * 16 + b_k) * 2);
                uint32_t r0, r1, r2, r3;
                LDM4(r0, r1, r2, r3, base + 2 * TILE_B + boff);
                bh[pair * 2][0] = r0; bh[pair * 2][1] = r1;
                bh[pair * 2 + 1][0] = r2; bh[pair * 2 + 1][1] = r3;
                LDM4(r0, r1, r2, r3, base + 3 * TILE_B + boff);
                bl[pair * 2][0] = r0; bl[pair * 2][1] = r1;
                bl[pair * 2 + 1][0] = r2; bl[pair * 2 + 1][1] = r3;
            }
#pragma unroll
            for (int mt = 0; mt < 4; mt++) {
                uint32_t aoff = (uint32_t)(((warp_m * 64 + mt * 16 + a_r) * 40 + kc * 16 + a_c) * 2);
                uint32_t ah[4], al[4];
                LDM4(ah[0], ah[1], ah[2], ah[3], base + aoff);
                LDM4(al[0], al[1], al[2], al[3], base + TILE_B + aoff);
#pragma unroll
                for (int nt = 0; nt < 4; nt++) {
                    MMA16816(acc[mt][nt], ah, bh[nt]);
                    MMA16816(acc[mt][nt], ah, bl[nt]);
                    MMA16816(acc[mt][nt], al, bh[nt]);
                }
            }
        }
        __syncthreads();
        if (s + 2 < NS) load_stage(s + 2);
    }

    // epilogue: direct float2 stores
    const int g = lane >> 2, tg = lane & 3;
#pragma unroll
    for (int mt = 0; mt < 4; mt++) {
#pragma unroll
        for (int nt = 0; nt < 4; nt++) {
            int col = n0 + warp_n * 32 + nt * 8 + tg * 2;
            if (col < Nc) {
                int r = row0 + warp_m * 64 + mt * 16 + g;
                *(float2*)&C[(size_t)r * Nc + col] = make_float2(acc[mt][nt][0], acc[mt][nt][1]);
                *(float2*)&C[(size_t)(r + 8) * Nc + col] = make_float2(acc[mt][nt][2], acc[mt][nt][3]);
            }
        }
    }
}

// ---------------- 3) depthwise conv + SiLU + RoPE + dt softplus ----------------
__global__ void __launch_bounds__(256) k_conv(const float* __restrict__ conv_w,
                                              const float* __restrict__ conv_b,
                                              const float* __restrict__ dt_bias) {
    const int row = blockIdx.x;
    const int l = row & (SEQ - 1);
    const int b = row >> 12;
    const int t = threadIdx.x;
    __shared__ float s[CONV_DIM];

    for (int ch = t; ch < CONV_DIM; ch += 256) {
        float acc = conv_b[ch];
#pragma unroll
        for (int i = 0; i < 4; i++) {
            int ls = l + i - 3;
            if (ls >= 0)
                acc += g_zx[(size_t)(b * SEQ + ls) * DPROJ + DI + ch] * conv_w[ch * 4 + i];
        }
        s[ch] = siluf(acc);
    }
    __syncthreads();

    float r1 = 0.f, r2 = 0.f;
    int jb = 0;
    if (t < 64) {
        int which = t >> 5;
        int j = t & 31;
        jb = DI + which * DS + j;
        float freq = powf(10000.f, -(float)j / 32.f);
        float ang = (float)l * freq;
        float sn, cs;
        sincosf(ang, &sn, &cs);
        float v1 = s[jb], v2 = s[jb + 32];
        r1 = v1 * cs - v2 * sn;
        r2 = v1 * sn + v2 * cs;
    }
    __syncthreads();
    if (t < 64) { s[jb] = r1; s[jb + 32] = r2; }
    __syncthreads();

    float* dst = g_xbc + (size_t)row * CONV_DIM;
    for (int ch = t; ch < CONV_DIM; ch += 256) dst[ch] = s[ch];

    if (t < NH) {
        float v = g_zx[(size_t)row * DPROJ + DT_OFF + t] + dt_bias[t];
        g_dt[(size_t)row * NH + t] = (v > 20.f) ? v : log1pf(expf(v));
    }
}

// ---------------- 4) intra-chunk ----------------
__global__ void __launch_bounds__(256) k_chunk(const float* __restrict__ A_log) {
    const int h = blockIdx.x, c = blockIdx.y, b = blockIdx.z;
    __shared__ float Bs[32][129];
    __shared__ float Cs[32][129];
    __shared__ float Xs[32][65];
    __shared__ float att[32][33];
    __shared__ float dts[32], dacs[32], coeff[32];
    const int t = threadIdx.x;
    const int row0 = b * SEQ + c * CHK;

    for (int idx = t; idx < 32 * 128; idx += 256) {
        int i = idx >> 7, n = idx & 127;
        size_t g = (size_t)(row0 + i) * CONV_DIM;
        Bs[i][n] = g_xbc[g + DI + n];
        Cs[i][n] = g_xbc[g + DI + DS + n];
    }
    for (int idx = t; idx < 32 * 64; idx += 256) {
        int i = idx >> 6, p = idx & 63;
        Xs[i][p] = g_xbc[(size_t)(row0 + i) * CONV_DIM + h * HD + p];
    }
    if (t < 32) dts[t] = g_dt[(size_t)(row0 + t) * NH + h];
    __syncthreads();
    if (t == 0) {
        float A = -expf(A_log[h]);
        float cs = 0.f;
        for (int i = 0; i < 32; i++) { cs += dts[i] * A; dacs[i] = cs; }
    }
    __syncthreads();
    if (t < 32) coeff[t] = dts[t] * expf(dacs[31] - dacs[t]);

    {
        int i = t >> 3, j0 = (t & 7) << 2;
        float s0 = 0, s1 = 0, s2 = 0, s3 = 0;
        for (int n = 0; n < 128; n++) {
            float cv = Cs[i][n];
            s0 += cv * Bs[j0 + 0][n];
            s1 += cv * Bs[j0 + 1][n];
            s2 += cv * Bs[j0 + 2][n];
            s3 += cv * Bs[j0 + 3][n];
        }
        float di = dacs[i];
        att[i][j0 + 0] = (j0 + 0 <= i) ? s0 * expf(di - dacs[j0 + 0]) * dts[j0 + 0] : 0.f;
        att[i][j0 + 1] = (j0 + 1 <= i) ? s1 * expf(di - dacs[j0 + 1]) * dts[j0 + 1] : 0.f;
        att[i][j0 + 2] = (j0 + 2 <= i) ? s2 * expf(di - dacs[j0 + 2]) * dts[j0 + 2] : 0.f;
        att[i][j0 + 3] = (j0 + 3 <= i) ? s3 * expf(di - dacs[j0 + 3]) * dts[j0 + 3] : 0.f;
    }
    __syncthreads();

    {
        int i = t >> 3, p0 = (t & 7) << 3;
        float acc[8] = {0, 0, 0, 0, 0, 0, 0, 0};
        for (int j = 0; j <= i; j++) {
            float a = att[i][j];
#pragma unroll
            for (int q = 0; q < 8; q++) acc[q] += a * Xs[j][p0 + q];
        }
        size_t g = (size_t)(row0 + i) * DI + h * HD + p0;
#pragma unroll
        for (int q = 0; q < 8; q++) g_yv[g + q] = acc[q];
    }

    {
        int n = t & 127;
        int pb = t >> 7;
        float Bv[32];
#pragma unroll
        for (int l = 0; l < 32; l++) Bv[l] = coeff[l] * Bs[l][n];
        size_t sb = ((size_t)((b * NC + c) * NH + h)) * (HD * DS);
        for (int e = 0; e < 32; e++) {
            int p = pb + 2 * e;
            float s = 0.f;
#pragma unroll
            for (int l = 0; l < 32; l++) s += Bv[l] * Xs[l][p];
            g_states[sb + (size_t)p * DS + n] = s;
        }
    }
    if (t == 0) g_cd[(b * NC + c) * NH + h] = expf(dacs[31]);
}

// ---------------- 5) inter-chunk scan ----------------
__global__ void __launch_bounds__(256) k_scan() {
    const int bh = blockIdx.x;
    const int b = bh / NH, h = bh % NH;
    const int t = threadIdx.x;
    float s[32];
#pragma unroll
    for (int e = 0; e < 32; e++) s[e] = 0.f;
    for (int c = 0; c < NC; c++) {
        size_t base = ((size_t)((b * NC + c) * NH + h)) * (HD * DS);
        float cdv = g_cd[(b * NC + c) * NH + h];
#pragma unroll
        for (int e = 0; e < 32; e++) {
            size_t off = base + (size_t)e * 256 + t;
            float tmp = g_states[off];
            g_states[off] = s[e];
            s[e] = s[e] * cdv + tmp;
        }
    }
}

// ---------------- 6) Yo + gate -> yv bf16 hi/lo ----------------
__global__ void __launch_bounds__(256) k_yo(const float* __restrict__ A_log,
                                            const float* __restrict__ Dp) {
    const int h = blockIdx.x, c = blockIdx.y, b = blockIdx.z;
    __shared__ float Cs[32][129];
    __shared__ float Ps[64][65];
    __shared__ float dts[32], dacs[32];
    const int t = threadIdx.x;
    const int row0 = b * SEQ + c * CHK;

    for (int idx = t; idx < 32 * 128; idx += 256) {
        int i = idx >> 7, n = idx & 127;
        Cs[i][n] = g_xbc[(size_t)(row0 + i) * CONV_DIM + DI + DS + n];
    }
    if (t < 32) dts[t] = g_dt[(size_t)(row0 + t) * NH + h];
    __syncthreads();
    if (t == 0) {
        float A = -expf(A_log[h]);
        float cs = 0.f;
        for (int i = 0; i < 32; i++) { cs += dts[i] * A; dacs[i] = cs; }
    }

    const int i = t >> 3, p0 = (t & 7) << 3;
    float acc[8] = {0, 0, 0, 0, 0, 0, 0, 0};
    size_t pb = ((size_t)((b * NC + c) * NH + h)) * (HD * DS);
    for (int half = 0; half < 2; half++) {
        __syncthreads();
        for (int idx = t; idx < 64 * 64; idx += 256) {
            int p = idx >> 6, n = idx & 63;
            Ps[p][n] = g_states[pb + (size_t)p * DS + half * 64 + n];
        }
        __syncthreads();
        for (int n = 0; n < 64; n++) {
            float cv = Cs[i][half * 64 + n];
#pragma unroll
            for (int q = 0; q < 8; q++) acc[q] += cv * Ps[p0 + q][n];
        }
    }
    float ei = expf(dacs[i]);
    float dph = Dp[h];
    size_t row = row0 + i;
#pragma unroll
    for (int q = 0; q < 8; q++) {
        int p = p0 + q;
        float xin = g_xbc[row * CONV_DIM + h * HD + p];
        float z = g_zx[row * DPROJ + h * HD + p];
        size_t yi = row * DI + h * HD + p;
        float Y = g_yv[yi] + ei * acc[q] + dph * xin;
        float outv = Y * siluf(z);
        split2(outv, g_yv_h[yi], g_yv_l[yi]);
    }
}

// ---------------- 8) post-RMSNorm + residual ----------------
__global__ void __launch_bounds__(256) k_final(const float* __restrict__ x,
                                               const float* __restrict__ sc,
                                               float* __restrict__ out) {
    int row = blockIdx.x, t = threadIdx.x;
    const float* gr = g_out + (size_t)row * DM;
    float v0 = gr[t], v1 = gr[t + 256], v2 = gr[t + 512];
    float ss = block_reduce_sum(v0 * v0 + v1 * v1 + v2 * v2);
    float inv = rsqrtf(ss * (1.0f / DM) + EPS);
    const float* xr = x + (size_t)row * DM;
    size_t o = (size_t)row * DM;
    out[o + t]       = xr[t]       + v0 * inv * (1.f + sc[t]);
    out[o + t + 256] = xr[t + 256] + v1 * inv * (1.f + sc[t + 256]);
    out[o + t + 512] = xr[t + 512] + v2 * inv * (1.f + sc[t + 512]);
}

// ---------------- launch -----------------------------------------------------
extern "C" void kernel_launch(void* const* d_in, const int* in_sizes, int n_in,
                              void* d_out, int out_size) {
    const float* x          = (const float*)d_in[0];
    const float* pre_scale  = (const float*)d_in[1];
    const float* post_scale = (const float*)d_in[2];
    const float* W_in       = (const float*)d_in[3];
    const float* conv_w     = (const float*)d_in[4];
    const float* conv_b     = (const float*)d_in[5];
    const float* dt_bias    = (const float*)d_in[6];
    const float* A_log      = (const float*)d_in[7];
    const float* D_param    = (const float*)d_in[8];
    const float* W_out      = (const float*)d_in[9];
    float* out = (float*)d_out;

    static int configured = 0;
    if (!configured) {
        cudaFuncSetAttribute(k_gemm_mma<768>,  cudaFuncAttributeMaxDynamicSharedMemorySize, SMEM_GEMM_BYTES);
        cudaFuncSetAttribute(k_gemm_mma<1536>, cudaFuncAttributeMaxDynamicSharedMemorySize, SMEM_GEMM_BYTES);
        configured = 1;
    }

    __nv_bfloat16 *yh, *yl, *winh, *winl, *wouth, *woutl, *yvh, *yvl;
    float *zx, *outp;
    cudaGetSymbolAddress((void**)&yh, g_y_h);
    cudaGetSymbolAddress((void**)&yl, g_y_l);
    cudaGetSymbolAddress((void**)&winh, g_winT_h);
    cudaGetSymbolAddress((void**)&winl, g_winT_l);
    cudaGetSymbolAddress((void**)&wouth, g_woutT_h);
    cudaGetSymbolAddress((void**)&woutl, g_woutT_l);
    cudaGetSymbolAddress((void**)&yvh, g_yv_h);
    cudaGetSymbolAddress((void**)&yvl, g_yv_l);
    cudaGetSymbolAddress((void**)&zx, g_zx);
    cudaGetSymbolAddress((void**)&outp, g_out);

    k_rms_pre<<<ROWS, 256>>>(x, pre_scale);
    k_wsplit<<<dim3(N1PAD / 32, DM / 32), 256>>>(W_in, winh, winl, DM, DPROJ, N1PAD);
    k_gemm_mma<768><<<dim3(N1PAD / 128, ROWS / 128), 256, SMEM_GEMM_BYTES>>>(yh, yl, winh, winl, zx, DPROJ);
    k_conv<<<ROWS, 256>>>(conv_w, conv_b, dt_bias);
    k_chunk<<<dim3(NH, NC, BATCH), 256>>>(A_log);
    k_scan<<<BATCH * NH, 256>>>();
    k_wsplit<<<dim3(DM / 32, DI / 32), 256>>>(W_out, wouth, woutl, DI, DM, DM);
    k_yo<<<dim3(NH, NC, BATCH), 256>>>(A_log, D_param);
    k_gemm_mma<1536><<<dim3(DM / 128, ROWS / 128), 256, SMEM_GEMM_BYTES>>>(yvh, yvl, wouth, woutl, outp, DM);
    k_final<<<ROWS, 256>>>(x, post_scale, out);
}

// round 6
// speedup vs baseline: 1.5062x; 1.0317x over previous
#include <cuda_runtime.h>
#include <cuda_bf16.h>
#include <math.h>
#include <stdint.h>

// ---------------- problem constants ----------------
#define BATCH 2
#define SEQ   4096
#define DM    768
#define DI    1536
#define NH    24
#define HD    64
#define DS    128
#define CHK   32
#define NC    128
#define CONV_DIM 1792
#define DPROJ 3352
#define DT_OFF 3328
#define ROWS  (BATCH*SEQ)
#define EPS   1e-6f

#define N1PAD 3456            // in_proj N padded to 27*128

// GEMM smem: 4 tiles (Ah,Al,Bh,Bl) x 128 rows x 80B, 3-stage pipeline
#define TILE_B  10240
#define STAGE_B (4*TILE_B)          // 40960
#define SMEM_GEMM_BYTES (3*STAGE_B) // 122880

// ---------------- scratch ----------------
__device__ __nv_bfloat16 g_y_h[(size_t)ROWS*DM];
__device__ __nv_bfloat16 g_y_l[(size_t)ROWS*DM];
__device__ __nv_bfloat16 g_winT_h[(size_t)N1PAD*DM];
__device__ __nv_bfloat16 g_winT_l[(size_t)N1PAD*DM];
__device__ __nv_bfloat16 g_woutT_h[(size_t)DM*DI];
__device__ __nv_bfloat16 g_woutT_l[(size_t)DM*DI];
__device__ __nv_bfloat16 g_yv_h[(size_t)ROWS*DI];
__device__ __nv_bfloat16 g_yv_l[(size_t)ROWS*DI];
__device__ float g_zx[(size_t)ROWS*DPROJ];
__device__ float g_xbc[(size_t)ROWS*CONV_DIM];
__device__ float g_dt[(size_t)ROWS*NH];
__device__ float g_states[(size_t)BATCH*NC*NH*HD*DS];
__device__ float g_cd[BATCH*NC*NH];
__device__ float g_cb[(size_t)BATCH*NC*CHK*CHK];   // head-invariant C.B^T per chunk
__device__ float g_yv[(size_t)ROWS*DI];        // Yd intermediate
__device__ float g_out[(size_t)ROWS*DM];

// ---------------- PTX helpers ----------------
__device__ __forceinline__ uint32_t smem_u32(const void* p) {
    uint32_t a;
    asm("{ .reg .u64 t; cvta.to.shared.u64 t, %1; cvt.u32.u64 %0, t; }" : "=r"(a) : "l"(p));
    return a;
}
#define CP16(dst, src)      asm volatile("cp.async.cg.shared.global [%0], [%1], 16;" :: "r"(dst), "l"(src))
#define CP_COMMIT()         asm volatile("cp.async.commit_group;" ::: "memory")
#define CP_WAIT1()          asm volatile("cp.async.wait_group 1;" ::: "memory")
#define CP_WAIT0()          asm volatile("cp.async.wait_group 0;" ::: "memory")

#define LDM4(r0, r1, r2, r3, addr) \
    asm volatile("ldmatrix.sync.aligned.m8n8.x4.shared.b16 {%0,%1,%2,%3}, [%4];" \
        : "=r"(r0), "=r"(r1), "=r"(r2), "=r"(r3) : "r"(addr))

#define MMA16816(c, a, b) \
    asm volatile("mma.sync.aligned.m16n8k16.row.col.f32.bf16.bf16.f32 " \
        "{%0,%1,%2,%3}, {%4,%5,%6,%7}, {%8,%9}, {%0,%1,%2,%3};" \
        : "+f"((c)[0]), "+f"((c)[1]), "+f"((c)[2]), "+f"((c)[3]) \
        : "r"((a)[0]), "r"((a)[1]), "r"((a)[2]), "r"((a)[3]), \
          "r"((b)[0]), "r"((b)[1]))

__device__ __forceinline__ void split2(float v, __nv_bfloat16& h, __nv_bfloat16& l) {
    h = __float2bfloat16_rn(v);
    l = __float2bfloat16_rn(v - __bfloat162float(h));
}
__device__ __forceinline__ float siluf(float x) { return x / (1.f + expf(-x)); }

__device__ __forceinline__ float block_reduce_sum(float v) {
    __shared__ float sh[8];
    int lane = threadIdx.x & 31, w = threadIdx.x >> 5;
#pragma unroll
    for (int o = 16; o; o >>= 1) v += __shfl_down_sync(0xffffffffu, v, o);
    if (lane == 0) sh[w] = v;
    __syncthreads();
    if (w == 0) {
        v = (lane < 8) ? sh[lane] : 0.f;
#pragma unroll
        for (int o = 4; o; o >>= 1) v += __shfl_down_sync(0xffffffffu, v, o);
        if (lane == 0) sh[0] = v;
    }
    __syncthreads();
    return sh[0];
}

// ---------------- 1) pre-RMSNorm -> bf16 hi/lo ----------------
__global__ void __launch_bounds__(256) k_rms_pre(const float* __restrict__ x,
                                                 const float* __restrict__ sc) {
    int row = blockIdx.x, t = threadIdx.x;
    const float* xr = x + (size_t)row * DM;
    float v0 = xr[t], v1 = xr[t + 256], v2 = xr[t + 512];
    float ss = block_reduce_sum(v0 * v0 + v1 * v1 + v2 * v2);
    float inv = rsqrtf(ss * (1.0f / DM) + EPS);
    __nv_bfloat16* yh = g_y_h + (size_t)row * DM;
    __nv_bfloat16* yl = g_y_l + (size_t)row * DM;
    float y0 = v0 * inv * (1.f + sc[t]);
    float y1 = v1 * inv * (1.f + sc[t + 256]);
    float y2 = v2 * inv * (1.f + sc[t + 512]);
    split2(y0, yh[t], yl[t]);
    split2(y1, yh[t + 256], yl[t + 256]);
    split2(y2, yh[t + 512], yl[t + 512]);
}

// ---------------- weight transpose + split ----------------
__global__ void __launch_bounds__(256) k_wsplit(const float* __restrict__ W,
                                                __nv_bfloat16* __restrict__ Th,
                                                __nv_bfloat16* __restrict__ Tl,
                                                int Kin, int Nin, int Npad) {
    __shared__ float tile[32][33];
    int tx = threadIdx.x & 31, ty = threadIdx.x >> 5;
    int n0 = blockIdx.x * 32, k0 = blockIdx.y * 32;
#pragma unroll
    for (int i = 0; i < 4; i++) {
        int k = k0 + ty + i * 8, n = n0 + tx;
        tile[ty + i * 8][tx] = (k < Kin && n < Nin) ? W[(size_t)k * Nin + n] : 0.f;
    }
    __syncthreads();
#pragma unroll
    for (int i = 0; i < 4; i++) {
        int n = n0 + ty + i * 8, k = k0 + tx;
        if (n < Npad && k < Kin) {
            float v = tile[tx][ty + i * 8];
            __nv_bfloat16 h, l;
            split2(v, h, l);
            Th[(size_t)n * Kin + k] = h;
            Tl[(size_t)n * Kin + k] = l;
        }
    }
}

// ---------------- bf16-split GEMM via mma.sync: C[M,Nc] = A[M,K] * B^T -------
// 3-stage cp.async pipeline: one __syncthreads per stage, loads issued before compute.
template <int K>
__global__ void __launch_bounds__(256) k_gemm_mma(const __nv_bfloat16* __restrict__ Ah,
                                                  const __nv_bfloat16* __restrict__ Al,
                                                  const __nv_bfloat16* __restrict__ Bh,
                                                  const __nv_bfloat16* __restrict__ Bl,
                                                  float* __restrict__ C, int Nc) {
    constexpr int NS = K / 32;
    extern __shared__ char smem[];
    const uint32_t sb = smem_u32(smem);
    const int tid = threadIdx.x;
    const int wid = tid >> 5, lane = tid & 31;
    const int warp_m = wid & 1, warp_n = wid >> 1;
    const int row0 = blockIdx.y * 128;
    const int n0   = blockIdx.x * 128;

    const __nv_bfloat16* srcs[4] = { Ah + (size_t)row0 * K, Al + (size_t)row0 * K,
                                     Bh + (size_t)n0  * K, Bl + (size_t)n0  * K };

    auto load_stage = [&](int s) {
        uint32_t base = sb + (uint32_t)(s % 3) * STAGE_B;
        int k0 = s * 32;
#pragma unroll
        for (int t4 = 0; t4 < 4; t4++) {
            const __nv_bfloat16* src = srcs[t4];
            uint32_t tb = base + (uint32_t)t4 * TILE_B;
#pragma unroll
            for (int it = 0; it < 2; it++) {
                int idx = it * 256 + tid;           // 0..511
                int r = idx >> 2, cs = idx & 3;
                CP16(tb + (uint32_t)(r * 80 + cs * 16), src + (size_t)r * K + k0 + cs * 8);
            }
        }
        CP_COMMIT();
    };

    load_stage(0);
    load_stage(1);

    float acc[4][4][4];
#pragma unroll
    for (int i = 0; i < 4; i++)
#pragma unroll
        for (int j = 0; j < 4; j++)
#pragma unroll
            for (int q = 0; q < 4; q++) acc[i][j][q] = 0.f;

    // per-lane ldmatrix offsets (elements)
    const int a_r = (lane & 7) + ((lane >> 3) & 1) * 8;
    const int a_c = ((lane >> 4) & 1) * 8;
    const int b_n = (lane & 7) + ((lane >> 4) & 1) * 8;
    const int b_k = ((lane >> 3) & 1) * 8;

    for (int s = 0; s < NS; s++) {
        if (s < NS - 1) { CP_WAIT1(); } else { CP_WAIT0(); }
        __syncthreads();
        if (s + 2 < NS) load_stage(s + 2);   // into buffer (s-1)%3, free since last sync
        uint32_t base = sb + (uint32_t)(s % 3) * STAGE_B;
#pragma unroll
        for (int kc = 0; kc < 2; kc++) {
            uint32_t bh[4][2], bl[4][2];
#pragma unroll
            for (int pair = 0; pair < 2; pair++) {
                uint32_t boff = (uint32_t)(((warp_n * 32 + pair * 16 + b_n) * 40 + kc * 16 + b_k) * 2);
                uint32_t r0, r1, r2, r3;
                LDM4(r0, r1, r2, r3, base + 2 * TILE_B + boff);
                bh[pair * 2][0] = r0; bh[pair * 2][1] = r1;
                bh[pair * 2 + 1][0] = r2; bh[pair * 2 + 1][1] = r3;
                LDM4(r0, r1, r2, r3, base + 3 * TILE_B + boff);
                bl[pair * 2][0] = r0; bl[pair * 2][1] = r1;
                bl[pair * 2 + 1][0] = r2; bl[pair * 2 + 1][1] = r3;
            }
#pragma unroll
            for (int mt = 0; mt < 4; mt++) {
                uint32_t aoff = (uint32_t)(((warp_m * 64 + mt * 16 + a_r) * 40 + kc * 16 + a_c) * 2);
                uint32_t ah[4], al[4];
                LDM4(ah[0], ah[1], ah[2], ah[3], base + aoff);
                LDM4(al[0], al[1], al[2], al[3], base + TILE_B + aoff);
#pragma unroll
                for (int nt = 0; nt < 4; nt++) {
                    MMA16816(acc[mt][nt], ah, bh[nt]);
                    MMA16816(acc[mt][nt], ah, bl[nt]);
                    MMA16816(acc[mt][nt], al, bh[nt]);
                }
            }
        }
    }

    // epilogue: direct float2 stores
    const int g = lane >> 2, tg = lane & 3;
#pragma unroll
    for (int mt = 0; mt < 4; mt++) {
#pragma unroll
        for (int nt = 0; nt < 4; nt++) {
            int col = n0 + warp_n * 32 + nt * 8 + tg * 2;
            if (col < Nc) {
                int r = row0 + warp_m * 64 + mt * 16 + g;
                *(float2*)&C[(size_t)r * Nc + col] = make_float2(acc[mt][nt][0], acc[mt][nt][1]);
                *(float2*)&C[(size_t)(r + 8) * Nc + col] = make_float2(acc[mt][nt][2], acc[mt][nt][3]);
            }
        }
    }
}

// ---------------- 3) depthwise conv + SiLU + RoPE + dt softplus ----------------
__global__ void __launch_bounds__(256) k_conv(const float* __restrict__ conv_w,
                                              const float* __restrict__ conv_b,
                                              const float* __restrict__ dt_bias) {
    const int row = blockIdx.x;
    const int l = row & (SEQ - 1);
    const int b = row >> 12;
    const int t = threadIdx.x;
    __shared__ float s[CONV_DIM];

    for (int ch = t; ch < CONV_DIM; ch += 256) {
        float acc = conv_b[ch];
#pragma unroll
        for (int i = 0; i < 4; i++) {
            int ls = l + i - 3;
            if (ls >= 0)
                acc += g_zx[(size_t)(b * SEQ + ls) * DPROJ + DI + ch] * conv_w[ch * 4 + i];
        }
        s[ch] = siluf(acc);
    }
    __syncthreads();

    float r1 = 0.f, r2 = 0.f;
    int jb = 0;
    if (t < 64) {
        int which = t >> 5;
        int j = t & 31;
        jb = DI + which * DS + j;
        float freq = powf(10000.f, -(float)j / 32.f);
        float ang = (float)l * freq;
        float sn, cs;
        sincosf(ang, &sn, &cs);
        float v1 = s[jb], v2 = s[jb + 32];
        r1 = v1 * cs - v2 * sn;
        r2 = v1 * sn + v2 * cs;
    }
    __syncthreads();
    if (t < 64) { s[jb] = r1; s[jb + 32] = r2; }
    __syncthreads();

    float* dst = g_xbc + (size_t)row * CONV_DIM;
    for (int ch = t; ch < CONV_DIM; ch += 256) dst[ch] = s[ch];

    if (t < NH) {
        float v = g_zx[(size_t)row * DPROJ + DT_OFF + t] + dt_bias[t];
        g_dt[(size_t)row * NH + t] = (v > 20.f) ? v : log1pf(expf(v));
    }
}

// ---------------- 3.5) head-invariant CB[i][j] = C_i . B_j per chunk ----------
__global__ void __launch_bounds__(256) k_cb() {
    const int cb = blockIdx.x;          // b*NC + c
    const int t = threadIdx.x;
    __shared__ float Bs[32][129];
    __shared__ float Cs[32][129];
    const int row0 = cb * CHK;          // == b*SEQ + c*CHK since SEQ = NC*CHK

    for (int idx = t; idx < 32 * 128; idx += 256) {
        int i = idx >> 7, n = idx & 127;
        size_t g = (size_t)(row0 + i) * CONV_DIM;
        Bs[i][n] = g_xbc[g + DI + n];
        Cs[i][n] = g_xbc[g + DI + DS + n];
    }
    __syncthreads();

    int i = t >> 3, j0 = (t & 7) << 2;
    float s0 = 0, s1 = 0, s2 = 0, s3 = 0;
    for (int n = 0; n < 128; n++) {
        float cv = Cs[i][n];
        s0 += cv * Bs[j0 + 0][n];
        s1 += cv * Bs[j0 + 1][n];
        s2 += cv * Bs[j0 + 2][n];
        s3 += cv * Bs[j0 + 3][n];
    }
    float* dst = g_cb + (size_t)cb * (CHK * CHK) + i * CHK + j0;
    dst[0] = s0; dst[1] = s1; dst[2] = s2; dst[3] = s3;
}

// ---------------- 4) intra-chunk: Yd + states (att from precomputed CB) --------
__global__ void __launch_bounds__(256) k_chunk(const float* __restrict__ A_log) {
    const int h = blockIdx.x, c = blockIdx.y, b = blockIdx.z;
    __shared__ float Bs[32][129];
    __shared__ float Xs[32][65];
    __shared__ float att[32][33];
    __shared__ float dts[32], dacs[32], coeff[32];
    const int t = threadIdx.x;
    const int row0 = b * SEQ + c * CHK;
    const int cb = b * NC + c;

    for (int idx = t; idx < 32 * 128; idx += 256) {
        int i = idx >> 7, n = idx & 127;
        Bs[i][n] = g_xbc[(size_t)(row0 + i) * CONV_DIM + DI + n];
    }
    for (int idx = t; idx < 32 * 64; idx += 256) {
        int i = idx >> 6, p = idx & 63;
        Xs[i][p] = g_xbc[(size_t)(row0 + i) * CONV_DIM + h * HD + p];
    }
    if (t < 32) dts[t] = g_dt[(size_t)(row0 + t) * NH + h];
    __syncthreads();
    if (t == 0) {
        float A = -expf(A_log[h]);
        float cs = 0.f;
        for (int i = 0; i < 32; i++) { cs += dts[i] * A; dacs[i] = cs; }
    }
    __syncthreads();
    if (t < 32) coeff[t] = dts[t] * expf(dacs[31] - dacs[t]);

    // att[i][j] = CB[i][j] * exp(dacs_i - dacs_j) * dt_j for j<=i
    {
        const float* cbp = g_cb + (size_t)cb * (CHK * CHK);
        for (int idx = t; idx < 1024; idx += 256) {
            int i = idx >> 5, j = idx & 31;
            att[i][j] = (j <= i) ? cbp[idx] * expf(dacs[i] - dacs[j]) * dts[j] : 0.f;
        }
    }
    __syncthreads();

    {
        int i = t >> 3, p0 = (t & 7) << 3;
        float acc[8] = {0, 0, 0, 0, 0, 0, 0, 0};
        for (int j = 0; j <= i; j++) {
            float a = att[i][j];
#pragma unroll
            for (int q = 0; q < 8; q++) acc[q] += a * Xs[j][p0 + q];
        }
        size_t g = (size_t)(row0 + i) * DI + h * HD + p0;
#pragma unroll
        for (int q = 0; q < 8; q++) g_yv[g + q] = acc[q];
    }

    {
        int n = t & 127;
        int pb = t >> 7;
        float Bv[32];
#pragma unroll
        for (int l = 0; l < 32; l++) Bv[l] = coeff[l] * Bs[l][n];
        size_t sb = ((size_t)((b * NC + c) * NH + h)) * (HD * DS);
        for (int e = 0; e < 32; e++) {
            int p = pb + 2 * e;
            float s = 0.f;
#pragma unroll
            for (int l = 0; l < 32; l++) s += Bv[l] * Xs[l][p];
            g_states[sb + (size_t)p * DS + n] = s;
        }
    }
    if (t == 0) g_cd[(b * NC + c) * NH + h] = expf(dacs[31]);
}

// ---------------- 5) inter-chunk scan ----------------
__global__ void __launch_bounds__(256) k_scan() {
    const int bh = blockIdx.x;
    const int b = bh / NH, h = bh % NH;
    const int t = threadIdx.x;
    float s[32];
#pragma unroll
    for (int e = 0; e < 32; e++) s[e] = 0.f;
    for (int c = 0; c < NC; c++) {
        size_t base = ((size_t)((b * NC + c) * NH + h)) * (HD * DS);
        float cdv = g_cd[(b * NC + c) * NH + h];
#pragma unroll
        for (int e = 0; e < 32; e++) {
            size_t off = base + (size_t)e * 256 + t;
            float tmp = g_states[off];
            g_states[off] = s[e];
            s[e] = s[e] * cdv + tmp;
        }
    }
}

// ---------------- 6) Yo + gate -> yv bf16 hi/lo ----------------
__global__ void __launch_bounds__(256) k_yo(const float* __restrict__ A_log,
                                            const float* __restrict__ Dp) {
    const int h = blockIdx.x, c = blockIdx.y, b = blockIdx.z;
    __shared__ float Cs[32][129];
    __shared__ float Ps[64][65];
    __shared__ float dts[32], dacs[32];
    const int t = threadIdx.x;
    const int row0 = b * SEQ + c * CHK;

    for (int idx = t; idx < 32 * 128; idx += 256) {
        int i = idx >> 7, n = idx & 127;
        Cs[i][n] = g_xbc[(size_t)(row0 + i) * CONV_DIM + DI + DS + n];
    }
    if (t < 32) dts[t] = g_dt[(size_t)(row0 + t) * NH + h];
    __syncthreads();
    if (t == 0) {
        float A = -expf(A_log[h]);
        float cs = 0.f;
        for (int i = 0; i < 32; i++) { cs += dts[i] * A; dacs[i] = cs; }
    }

    const int i = t >> 3, p0 = (t & 7) << 3;
    float acc[8] = {0, 0, 0, 0, 0, 0, 0, 0};
    size_t pb = ((size_t)((b * NC + c) * NH + h)) * (HD * DS);
    for (int half = 0; half < 2; half++) {
        __syncthreads();
        for (int idx = t; idx < 64 * 64; idx += 256) {
            int p = idx >> 6, n = idx & 63;
            Ps[p][n] = g_states[pb + (size_t)p * DS + half * 64 + n];
        }
        __syncthreads();
        for (int n = 0; n < 64; n++) {
            float cv = Cs[i][half * 64 + n];
#pragma unroll
            for (int q = 0; q < 8; q++) acc[q] += cv * Ps[p0 + q][n];
        }
    }
    float ei = expf(dacs[i]);
    float dph = Dp[h];
    size_t row = row0 + i;
#pragma unroll
    for (int q = 0; q < 8; q++) {
        int p = p0 + q;
        float xin = g_xbc[row * CONV_DIM + h * HD + p];
        float z = g_zx[row * DPROJ + h * HD + p];
        size_t yi = row * DI + h * HD + p;
        float Y = g_yv[yi] + ei * acc[q] + dph * xin;
        float outv = Y * siluf(z);
        split2(outv, g_yv_h[yi], g_yv_l[yi]);
    }
}

// ---------------- 8) post-RMSNorm + residual ----------------
__global__ void __launch_bounds__(256) k_final(const float* __restrict__ x,
                                               const float* __restrict__ sc,
                                               float* __restrict__ out) {
    int row = blockIdx.x, t = threadIdx.x;
    const float* gr = g_out + (size_t)row * DM;
    float v0 = gr[t], v1 = gr[t + 256], v2 = gr[t + 512];
    float ss = block_reduce_sum(v0 * v0 + v1 * v1 + v2 * v2);
    float inv = rsqrtf(ss * (1.0f / DM) + EPS);
    const float* xr = x + (size_t)row * DM;
    size_t o = (size_t)row * DM;
    out[o + t]       = xr[t]       + v0 * inv * (1.f + sc[t]);
    out[o + t + 256] = xr[t + 256] + v1 * inv * (1.f + sc[t + 256]);
    out[o + t + 512] = xr[t + 512] + v2 * inv * (1.f + sc[t + 512]);
}

// ---------------- launch -----------------------------------------------------
extern "C" void kernel_launch(void* const* d_in, const int* in_sizes, int n_in,
                              void* d_out, int out_size) {
    const float* x          = (const float*)d_in[0];
    const float* pre_scale  = (const float*)d_in[1];
    const float* post_scale = (const float*)d_in[2];
    const float* W_in       = (const float*)d_in[3];
    const float* conv_w     = (const float*)d_in[4];
    const float* conv_b     = (const float*)d_in[5];
    const float* dt_bias    = (const float*)d_in[6];
    const float* A_log      = (const float*)d_in[7];
    const float* D_param    = (const float*)d_in[8];
    const float* W_out      = (const float*)d_in[9];
    float* out = (float*)d_out;

    static int configured = 0;
    if (!configured) {
        cudaFuncSetAttribute(k_gemm_mma<768>,  cudaFuncAttributeMaxDynamicSharedMemorySize, SMEM_GEMM_BYTES);
        cudaFuncSetAttribute(k_gemm_mma<1536>, cudaFuncAttributeMaxDynamicSharedMemorySize, SMEM_GEMM_BYTES);
        configured = 1;
    }

    __nv_bfloat16 *yh, *yl, *winh, *winl, *wouth, *woutl, *yvh, *yvl;
    float *zx, *outp;
    cudaGetSymbolAddress((void**)&yh, g_y_h);
    cudaGetSymbolAddress((void**)&yl, g_y_l);
    cudaGetSymbolAddress((void**)&winh, g_winT_h);
    cudaGetSymbolAddress((void**)&winl, g_winT_l);
    cudaGetSymbolAddress((void**)&wouth, g_woutT_h);
    cudaGetSymbolAddress((void**)&woutl, g_woutT_l);
    cudaGetSymbolAddress((void**)&yvh, g_yv_h);
    cudaGetSymbolAddress((void**)&yvl, g_yv_l);
    cudaGetSymbolAddress((void**)&zx, g_zx);
    cudaGetSymbolAddress((void**)&outp, g_out);

    k_rms_pre<<<ROWS, 256>>>(x, pre_scale);
    k_wsplit<<<dim3(N1PAD / 32, DM / 32), 256>>>(W_in, winh, winl, DM, DPROJ, N1PAD);
    k_gemm_mma<768><<<dim3(N1PAD / 128, ROWS / 128), 256, SMEM_GEMM_BYTES>>>(yh, yl, winh, winl, zx, DPROJ);
    k_conv<<<ROWS, 256>>>(conv_w, conv_b, dt_bias);
    k_cb<<<BATCH * NC, 256>>>();
    k_chunk<<<dim3(NH, NC, BATCH), 256>>>(A_log);
    k_scan<<<BATCH * NH, 256>>>();
    k_wsplit<<<dim3(DM / 32, DI / 32), 256>>>(W_out, wouth, woutl, DI, DM, DM);
    k_yo<<<dim3(NH, NC, BATCH), 256>>>(A_log, D_param);
    k_gemm_mma<1536><<<dim3(DM / 128, ROWS / 128), 256, SMEM_GEMM_BYTES>>>(yvh, yvl, wouth, woutl, outp, DM);
    k_final<<<ROWS, 256>>>(x, post_scale, out);
}